// round 15
// baseline (speedup 1.0000x reference)
#include <cuda_runtime.h>
#include <cuda_fp16.h>
#include <math.h>
#include <stdint.h>

#define WSZ 8
#define NHEAD 4
#define DIM 128
#define NTOK 64
#define HD 32
#define BATCH 32
#define HW 64
#define LSEQ 4096
#define RPE_HID 512
#define APAD 132
#define YPH 136    // fp16 smem pitch (halves)
#define PPH 72     // Vt fp16 pitch (halves)

__device__ float g_bias[NHEAD * NTOK * NTOK];
__device__ float g_ttab[225 * NHEAD];
__device__ float g_ybuf[(size_t)BATCH * LSEQ * DIM];
__device__ __half g_qkvw_h[3 * DIM * DIM];
__device__ __half g_projw_h[DIM * DIM];
__device__ __half g_fc1w_h[512 * DIM];
__device__ __half g_fc2w_h[DIM * 512];

// ---------------- fp16 MMA + ldmatrix helpers ----------------
__device__ __forceinline__ void mma_f16(float* c, const uint32_t* a, uint32_t b0, uint32_t b1) {
    asm volatile(
        "mma.sync.aligned.m16n8k16.row.col.f32.f16.f16.f32 "
        "{%0,%1,%2,%3}, {%4,%5,%6,%7}, {%8,%9}, {%0,%1,%2,%3};"
        : "+f"(c[0]), "+f"(c[1]), "+f"(c[2]), "+f"(c[3])
        : "r"(a[0]), "r"(a[1]), "r"(a[2]), "r"(a[3]), "r"(b0), "r"(b1));
}

__device__ __forceinline__ void ldsm_x4(uint32_t& r0, uint32_t& r1, uint32_t& r2, uint32_t& r3,
                                        uint32_t addr) {
    asm volatile("ldmatrix.sync.aligned.m8n8.x4.shared.b16 {%0,%1,%2,%3}, [%4];"
                 : "=r"(r0), "=r"(r1), "=r"(r2), "=r"(r3) : "r"(addr));
}

template<int MT, int NT, int KS>
__device__ __forceinline__ void wgemm_l(const __half* __restrict__ A, int lda,
                                        const __half* __restrict__ B, int ldb,
                                        float (&acc)[MT][NT][4], int rbase, int nbase, int lane)
{
    int lr = lane & 15;
    int lk = (lane >> 4) << 3;
    uint32_t ab[MT], bb[NT / 2];
    #pragma unroll
    for (int m = 0; m < MT; m++)
        ab[m] = (uint32_t)__cvta_generic_to_shared(A + (rbase + m * 16 + lr) * lda + lk);
    #pragma unroll
    for (int nn = 0; nn < NT / 2; nn++)
        bb[nn] = (uint32_t)__cvta_generic_to_shared(B + (nbase + nn * 16 + lr) * ldb + lk);
    #pragma unroll
    for (int ks = 0; ks < KS; ks++) {
        uint32_t a[MT][4];
        #pragma unroll
        for (int m = 0; m < MT; m++)
            ldsm_x4(a[m][0], a[m][1], a[m][2], a[m][3], ab[m] + ks * 32);
        #pragma unroll
        for (int nn = 0; nn < NT / 2; nn++) {
            uint32_t b0, b1, b2, b3;
            ldsm_x4(b0, b1, b2, b3, bb[nn] + ks * 32);
            #pragma unroll
            for (int m = 0; m < MT; m++) {
                mma_f16(acc[m][2 * nn],     a[m], b0, b2);
                mma_f16(acc[m][2 * nn + 1], a[m], b1, b3);
            }
        }
    }
}

// ---------------- cp.async helpers ----------------
__device__ __forceinline__ void cp16(uint32_t dst, const void* src) {
    asm volatile("cp.async.ca.shared.global [%0], [%1], 16;" :: "r"(dst), "l"(src));
}
__device__ __forceinline__ void cp_commit() { asm volatile("cp.async.commit_group;"); }
__device__ __forceinline__ void cp_wait0()  { asm volatile("cp.async.wait_group 0;"); }

// ---------------- fused prep: RPE table + weight fp16 conversion ----------------
__global__ void prep_fused_kernel(const float* __restrict__ qkvw, const float* __restrict__ projw,
                                  const float* __restrict__ fc1w, const float* __restrict__ fc2w,
                                  const float* __restrict__ w1, const float* __restrict__ b1,
                                  const float* __restrict__ w2) {
    int tid = threadIdx.x;
    if (blockIdx.x < 225) {
        __shared__ float4 red[128];
        int p = blockIdx.x;
        int i = p / 15, j = p % 15;
        float v0 = (float)(i - 7) / 7.0f * 8.0f;
        float v1 = (float)(j - 7) / 7.0f * 8.0f;
        float inv_l8 = 1.0f / log2f(8.0f);
        float s0 = (v0 > 0.f) ? 1.f : ((v0 < 0.f) ? -1.f : 0.f);
        float s1 = (v1 > 0.f) ? 1.f : ((v1 < 0.f) ? -1.f : 0.f);
        float x0 = s0 * log2f(fabsf(v0) + 1.0f) * inv_l8;
        float x1 = s1 * log2f(fabsf(v1) + 1.0f) * inv_l8;
        float a0 = 0.f, a1 = 0.f, a2 = 0.f, a3 = 0.f;
        #pragma unroll
        for (int r = 0; r < 4; r++) {
            int h = tid + 128 * r;
            float hid = x0 * w1[2 * h] + x1 * w1[2 * h + 1] + b1[h];
            hid = fmaxf(hid, 0.f);
            a0 += hid * w2[0 * RPE_HID + h];
            a1 += hid * w2[1 * RPE_HID + h];
            a2 += hid * w2[2 * RPE_HID + h];
            a3 += hid * w2[3 * RPE_HID + h];
        }
        red[tid] = make_float4(a0, a1, a2, a3);
        __syncthreads();
        for (int s = 64; s > 0; s >>= 1) {
            if (tid < s) {
                float4 o = red[tid + s];
                red[tid].x += o.x; red[tid].y += o.y; red[tid].z += o.z; red[tid].w += o.w;
            }
            __syncthreads();
        }
        if (tid == 0) {
            g_ttab[p * 4 + 0] = red[0].x; g_ttab[p * 4 + 1] = red[0].y;
            g_ttab[p * 4 + 2] = red[0].z; g_ttab[p * 4 + 3] = red[0].w;
        }
    } else {
        int e4 = (blockIdx.x - 225) * 128 + tid;   // 49152
        const float* src;
        __half* dst;
        int off;
        if (e4 < 12288)      { src = qkvw;  dst = g_qkvw_h;  off = e4; }
        else if (e4 < 16384) { src = projw; dst = g_projw_h; off = e4 - 12288; }
        else if (e4 < 32768) { src = fc1w;  dst = g_fc1w_h;  off = e4 - 16384; }
        else                 { src = fc2w;  dst = g_fc2w_h;  off = e4 - 32768; }
        float4 v = *(const float4*)(src + off * 4);
        *(__half2*)(dst + off * 4)     = __floats2half2_rn(v.x, v.y);
        *(__half2*)(dst + off * 4 + 2) = __floats2half2_rn(v.z, v.w);
    }
}

__global__ void bias_scatter_kernel() {
    int e = blockIdx.x * 256 + threadIdx.x;
    int h = e >> 12;
    int rem = e & 4095;
    int i = rem >> 6, j = rem & 63;
    int yi = i >> 3, xi = i & 7, yj = j >> 3, xj = j & 7;
    int idx = (yi - yj + 7) * 15 + (xi - xj + 7);
    g_bias[e] = g_ttab[idx * 4 + h];
}

// ---------------- Kernel 2: attention + LN1 + residual (2 windows/CTA, 512 threads) ----------------
#define AT_XW 0
#define AT_WB 34816
#define AT_QB 69632
#define AT_KB 104448
#define AT_VT 139264
#define AT_PS 176128
#define AT_RG 178176
#define AT_MU 178688
#define AT_RSTD 179200
#define ATTN_SMEM_BYTES 179712
#define VT_WSTRIDE 9216

__global__ __launch_bounds__(512, 1) void attn_kernel(
    const float* __restrict__ x, const float* __restrict__ qkv_b,
    const float* __restrict__ proj_b,
    const float* __restrict__ n1w, const float* __restrict__ n1b)
{
    extern __shared__ char smc[];
    __half* xw = (__half*)(smc + AT_XW);
    __half* ow = xw;
    __half* wb = (__half*)(smc + AT_WB);
    __half* qb = (__half*)(smc + AT_QB);
    __half* kb = (__half*)(smc + AT_KB);
    __half* vt = (__half*)(smc + AT_VT);
    float* ps = (float*)(smc + AT_PS);
    int* regid = (int*)(smc + AT_RG);
    float* mu = (float*)(smc + AT_MU);
    float* rstd = (float*)(smc + AT_RSTD);
    float* projf = (float*)(smc + AT_QB);   // overlay, pitch APAD, 128 rows

    uint32_t wbA = (uint32_t)__cvta_generic_to_shared(wb);

    int tid = threadIdx.x;
    int wid = tid >> 5;
    int lane = tid & 31;
    int g = lane >> 2;
    int i = lane & 3;

    int bx = blockIdx.x;
    int bimg = bx >> 5;
    int wpair = bx & 31;
    const float* xbase = x + (size_t)bimg * (LSEQ * DIM);

    // prefetch QKV chunk 0 -> wb
    #pragma unroll
    for (int it = 0; it < 4; it++) {
        int idx = tid + 512 * it;
        int r = idx >> 4;
        int col = (idx & 15) << 3;
        cp16(wbA + (r * YPH + col) * 2, g_qkvw_h + r * DIM + col);
    }
    cp_commit();

    // ---- load both windows (rolled -4) -> fp16 ----
    #pragma unroll
    for (int it = 0; it < 8; it++) {
        int e4 = tid + 512 * it;
        int row = e4 >> 5;
        int c = (e4 & 31) << 2;
        int wi = wpair * 2 + (row >> 6);
        int t = row & 63;
        int wh = wi >> 3, ww = wi & 7;
        int ti = t >> 3, tj = t & 7;
        int hh = (wh * 8 + ti + 4) & 63;
        int wwp = (ww * 8 + tj + 4) & 63;
        float4 v = *(const float4*)(xbase + (size_t)((hh << 6) + wwp) * DIM + c);
        *(__half2*)(xw + row * YPH + c)     = __floats2half2_rn(v.x, v.y);
        *(__half2*)(xw + row * YPH + c + 2) = __floats2half2_rn(v.z, v.w);
    }
    if (tid < 128) {
        int wi = wpair * 2 + (tid >> 6);
        int t = tid & 63;
        int wh = wi >> 3, ww = wi & 7;
        int ti = t >> 3, tj = t & 7;
        int ah = wh * 8 + ti, aw = ww * 8 + tj;
        int rh = ah < 56 ? 0 : (ah < 60 ? 1 : 2);
        int rw = aw < 56 ? 0 : (aw < 60 ? 1 : 2);
        regid[tid] = rh * 3 + rw;
    }

    const float scale = 0.17677669529663687f;

    // ---- QKV: 3 GEMMs 128x128 k=128, 16 warps 4Mx4N (32x32 tiles) ----
    for (int cidx = 0; cidx < 3; cidx++) {
        cp_wait0();
        __syncthreads();

        float acc[2][4][4];
        #pragma unroll
        for (int m = 0; m < 2; m++)
            #pragma unroll
            for (int n = 0; n < 4; n++)
                #pragma unroll
                for (int q = 0; q < 4; q++) acc[m][n][q] = 0.f;
        int rbase = (wid >> 2) * 32;
        int nbase = (wid & 3) * 32;
        wgemm_l<2, 4, 8>(xw, YPH, wb, YPH, acc, rbase, nbase, lane);
        __syncthreads();   // wb reads done before next prefetch overwrites

        {
            const __half* nsrc = (cidx < 2) ? (g_qkvw_h + (cidx + 1) * DIM * DIM) : g_projw_h;
            #pragma unroll
            for (int it = 0; it < 4; it++) {
                int idx = tid + 512 * it;
                int r = idx >> 4;
                int col = (idx & 15) << 3;
                cp16(wbA + (r * YPH + col) * 2, nsrc + r * DIM + col);
            }
            cp_commit();
        }

        #pragma unroll
        for (int n = 0; n < 4; n++) {
            int col = nbase + n * 8 + 2 * i;
            float b0f = qkv_b[cidx * DIM + col];
            float b1f = qkv_b[cidx * DIM + col + 1];
            #pragma unroll
            for (int m = 0; m < 2; m++) {
                int row = rbase + m * 16 + g;
                float v0 = acc[m][n][0] + b0f;
                float v1 = acc[m][n][1] + b1f;
                float v2 = acc[m][n][2] + b0f;
                float v3 = acc[m][n][3] + b1f;
                if (cidx == 0) {
                    *(__half2*)(qb + row * YPH + col)       = __floats2half2_rn(v0 * scale, v1 * scale);
                    *(__half2*)(qb + (row + 8) * YPH + col) = __floats2half2_rn(v2 * scale, v3 * scale);
                } else if (cidx == 1) {
                    *(__half2*)(kb + row * YPH + col)       = __floats2half2_rn(v0, v1);
                    *(__half2*)(kb + (row + 8) * YPH + col) = __floats2half2_rn(v2, v3);
                } else {
                    __half* vtw0 = vt + (row >> 6) * VT_WSTRIDE;
                    __half* vtw1 = vt + ((row + 8) >> 6) * VT_WSTRIDE;
                    int t0 = row & 63, t1 = (row + 8) & 63;
                    vtw0[col * PPH + t0]           = __float2half_rn(v0);
                    vtw0[(col + 1) * PPH + t0]     = __float2half_rn(v1);
                    vtw1[col * PPH + t1]           = __float2half_rn(v2);
                    vtw1[(col + 1) * PPH + t1]     = __float2half_rn(v3);
                }
            }
        }
        __syncthreads();
    }

    // ---- scores + register softmax + register P: warp -> (win, head, rowhalf) ----
    int win = wid >> 3;
    int h = (wid >> 1) & 3;
    int hoff = h * HD;
    int rbase_h = (wid & 1) * 32;
    const __half* qbw = qb + win * 64 * YPH;
    const __half* kbw = kb + win * 64 * YPH;
    const int* rg = regid + win * 64;
    uint32_t pr[2][2][8];
    float rsinv[2][2];
    {
        float s[2][8][4];
        #pragma unroll
        for (int m = 0; m < 2; m++)
            #pragma unroll
            for (int n = 0; n < 8; n++)
                #pragma unroll
                for (int q = 0; q < 4; q++) s[m][n][q] = 0.f;
        wgemm_l<2, 8, 2>(qbw + hoff, YPH, kbw + hoff, YPH, s, rbase_h, 0, lane);

        const float* gb = g_bias + h * 4096;
        int cmask[8][2];
        #pragma unroll
        for (int n = 0; n < 8; n++) {
            cmask[n][0] = rg[n * 8 + 2 * i];
            cmask[n][1] = rg[n * 8 + 2 * i + 1];
        }
        #pragma unroll
        for (int m = 0; m < 2; m++) {
            #pragma unroll
            for (int ss = 0; ss < 2; ss++) {
                int row = rbase_h + m * 16 + 8 * ss + g;
                int rreg = rg[row];
                const float* gbr = gb + row * 64;
                float v[16];
                float mx = -1e30f;
                #pragma unroll
                for (int n = 0; n < 8; n++) {
                    int col = n * 8 + 2 * i;
                    float a0 = s[m][n][2 * ss]     + gbr[col]     + ((rreg != cmask[n][0]) ? -100.f : 0.f);
                    float a1 = s[m][n][2 * ss + 1] + gbr[col + 1] + ((rreg != cmask[n][1]) ? -100.f : 0.f);
                    v[2 * n] = a0; v[2 * n + 1] = a1;
                    mx = fmaxf(mx, fmaxf(a0, a1));
                }
                mx = fmaxf(mx, __shfl_xor_sync(0xFFFFFFFF, mx, 1));
                mx = fmaxf(mx, __shfl_xor_sync(0xFFFFFFFF, mx, 2));
                float sum = 0.f;
                #pragma unroll
                for (int n = 0; n < 8; n++) {
                    float e0 = __expf(v[2 * n] - mx);
                    float e1 = __expf(v[2 * n + 1] - mx);
                    sum += e0 + e1;
                    __half2 hp = __floats2half2_rn(e0, e1);
                    pr[m][ss][n] = *(uint32_t*)&hp;
                }
                sum += __shfl_xor_sync(0xFFFFFFFF, sum, 1);
                sum += __shfl_xor_sync(0xFFFFFFFF, sum, 2);
                rsinv[m][ss] = 1.0f / sum;
            }
        }
    }

    // ---- PV from register P ----
    {
        float o[2][4][4];
        #pragma unroll
        for (int m = 0; m < 2; m++)
            #pragma unroll
            for (int n = 0; n < 4; n++)
                #pragma unroll
                for (int q = 0; q < 4; q++) o[m][n][q] = 0.f;
        const __half* Vb = vt + win * VT_WSTRIDE + hoff * PPH;
        int lr = lane & 15;
        int lk = (lane >> 4) << 3;
        uint32_t bb[2];
        #pragma unroll
        for (int nn = 0; nn < 2; nn++)
            bb[nn] = (uint32_t)__cvta_generic_to_shared(Vb + (nn * 16 + lr) * PPH + lk);
        #pragma unroll
        for (int ks = 0; ks < 4; ks++) {
            uint32_t a[2][4];
            #pragma unroll
            for (int m = 0; m < 2; m++) {
                a[m][0] = pr[m][0][2 * ks];
                a[m][1] = pr[m][1][2 * ks];
                a[m][2] = pr[m][0][2 * ks + 1];
                a[m][3] = pr[m][1][2 * ks + 1];
            }
            #pragma unroll
            for (int nn = 0; nn < 2; nn++) {
                uint32_t b0, b1, b2, b3;
                ldsm_x4(b0, b1, b2, b3, bb[nn] + ks * 32);
                #pragma unroll
                for (int m = 0; m < 2; m++) {
                    mma_f16(o[m][2 * nn],     a[m], b0, b2);
                    mma_f16(o[m][2 * nn + 1], a[m], b1, b3);
                }
            }
        }
        #pragma unroll
        for (int m = 0; m < 2; m++) {
            int row = win * 64 + rbase_h + m * 16 + g;
            float rs0 = rsinv[m][0];
            float rs1 = rsinv[m][1];
            #pragma unroll
            for (int n = 0; n < 4; n++) {
                int col = hoff + n * 8 + 2 * i;
                *(__half2*)(ow + row * YPH + col)       = __floats2half2_rn(o[m][n][0] * rs0, o[m][n][1] * rs0);
                *(__half2*)(ow + (row + 8) * YPH + col) = __floats2half2_rn(o[m][n][2] * rs1, o[m][n][3] * rs1);
            }
        }
    }
    cp_wait0();        // proj_w landed
    __syncthreads();

    // ---- proj GEMM 128x128 k=128 -> fp32 projf (overlays qb/kb) ----
    {
        float acc[2][4][4];
        #pragma unroll
        for (int m = 0; m < 2; m++)
            #pragma unroll
            for (int n = 0; n < 4; n++)
                #pragma unroll
                for (int q = 0; q < 4; q++) acc[m][n][q] = 0.f;
        int rbase = (wid >> 2) * 32;
        int nbase = (wid & 3) * 32;
        wgemm_l<2, 4, 8>(ow, YPH, wb, YPH, acc, rbase, nbase, lane);
        __syncthreads();   // all reads done before overlay write
        #pragma unroll
        for (int n = 0; n < 4; n++) {
            int col = nbase + n * 8 + 2 * i;
            float b0f = proj_b[col];
            float b1f = proj_b[col + 1];
            #pragma unroll
            for (int m = 0; m < 2; m++) {
                int row = rbase + m * 16 + g;
                projf[row * APAD + col]           = acc[m][n][0] + b0f;
                projf[row * APAD + col + 1]       = acc[m][n][1] + b1f;
                projf[(row + 8) * APAD + col]     = acc[m][n][2] + b0f;
                projf[(row + 8) * APAD + col + 1] = acc[m][n][3] + b1f;
            }
        }
    }
    __syncthreads();

    // ---- LN1 stats: 4 threads/row, 128 rows ----
    {
        int row = tid >> 2;
        int cb = (tid & 3) * 32;
        float s = 0.f;
        #pragma unroll 8
        for (int c = 0; c < 32; c++) s += projf[row * APAD + cb + c];
        ps[tid] = s;
    }
    __syncthreads();
    if (tid < 128) {
        float s = ps[4 * tid] + ps[4 * tid + 1] + ps[4 * tid + 2] + ps[4 * tid + 3];
        mu[tid] = s * (1.0f / DIM);
    }
    __syncthreads();
    {
        int row = tid >> 2;
        int cb = (tid & 3) * 32;
        float m = mu[row];
        float v = 0.f;
        #pragma unroll 8
        for (int c = 0; c < 32; c++) {
            float d = projf[row * APAD + cb + c] - m;
            v += d * d;
        }
        ps[tid] = v;
    }
    __syncthreads();
    if (tid < 128) {
        float v = ps[4 * tid] + ps[4 * tid + 1] + ps[4 * tid + 2] + ps[4 * tid + 3];
        rstd[tid] = rsqrtf(v * (1.0f / DIM) + 1e-5f);
    }
    __syncthreads();

    // ---- y = x + LN(proj), both windows ----
    float* yb = g_ybuf + (size_t)bimg * (LSEQ * DIM);
    #pragma unroll
    for (int it = 0; it < 8; it++) {
        int e4 = tid + 512 * it;
        int row = e4 >> 5;
        int c = (e4 & 31) << 2;
        int wi = wpair * 2 + (row >> 6);
        int t = row & 63;
        int wh = wi >> 3, ww = wi & 7;
        int ti = t >> 3, tj = t & 7;
        int hh = (wh * 8 + ti + 4) & 63;
        int wwp = (ww * 8 + tj + 4) & 63;
        size_t goff = (size_t)((hh << 6) + wwp) * DIM + c;
        float4 xv = *(const float4*)(xbase + goff);
        float m = mu[row], r = rstd[row];
        float4 o;
        o.x = xv.x + (projf[row * APAD + c + 0] - m) * r * n1w[c + 0] + n1b[c + 0];
        o.y = xv.y + (projf[row * APAD + c + 1] - m) * r * n1w[c + 1] + n1b[c + 1];
        o.z = xv.z + (projf[row * APAD + c + 2] - m) * r * n1w[c + 2] + n1b[c + 2];
        o.w = xv.w + (projf[row * APAD + c + 3] - m) * r * n1w[c + 3] + n1b[c + 3];
        *(float4*)(yb + goff) = o;
    }
}

// ---------------- Kernel 3: MLP + LN2 + residual (unchanged from R12) ----------------
#define MLP_SMEM_BYTES 142336

__global__ __launch_bounds__(512, 1) void mlp_kernel(
    const float* __restrict__ fc1b, const float* __restrict__ fc2b,
    const float* __restrict__ n2w, const float* __restrict__ n2b,
    float* __restrict__ out)
{
    extern __shared__ char smc[];
    __half* Yh = (__half*)smc;
    __half* Wa = (__half*)(smc + 34816);
    __half* Wb = (__half*)(smc + 69632);
    __half* Hh = (__half*)(smc + 104448);
    float* ps  = (float*)(smc + 139264);
    float* muv = ps + 512;
    float* rsv = muv + 128;
    float* h2  = (float*)smc;

    uint32_t WaA = (uint32_t)__cvta_generic_to_shared(Wa);
    uint32_t WbA = (uint32_t)__cvta_generic_to_shared(Wb);

    int tid = threadIdx.x;
    int wid = tid >> 5;
    int lane = tid & 31;
    int g = lane >> 2;
    int i = lane & 3;
    int rb = (wid >> 2) * 32;
    int nb = (wid & 3) * 32;

    size_t tok0 = (size_t)blockIdx.x * 128;
    const float* ysrc = g_ybuf + tok0 * DIM;

    #pragma unroll
    for (int it = 0; it < 4; it++) {
        int idx = tid + 512 * it;
        int r = idx >> 4;
        int col = (idx & 15) << 3;
        cp16(WaA + (r * YPH + col) * 2, g_fc1w_h + r * DIM + col);
    }
    cp_commit();

    #pragma unroll
    for (int it = 0; it < 8; it++) {
        int e4 = tid + 512 * it;
        int t = e4 >> 5;
        int c = (e4 & 31) << 2;
        float4 v = *(const float4*)(ysrc + (size_t)t * DIM + c);
        *(__half2*)(Yh + t * YPH + c)     = __floats2half2_rn(v.x, v.y);
        *(__half2*)(Yh + t * YPH + c + 2) = __floats2half2_rn(v.z, v.w);
    }

    float acc2[2][4][4];
    #pragma unroll
    for (int m = 0; m < 2; m++)
        #pragma unroll
        for (int n = 0; n < 4; n++)
            #pragma unroll
            for (int q = 0; q < 4; q++) acc2[m][n][q] = 0.f;

    const float is2 = 0.70710678118654752f;

    for (int hc = 0; hc < 4; hc++) {
        cp_wait0();
        __syncthreads();

        #pragma unroll
        for (int it = 0; it < 4; it++) {
            int idx = tid + 512 * it;
            int r = idx >> 4;
            int col = (idx & 15) << 3;
            cp16(WbA + (r * YPH + col) * 2, g_fc2w_h + (size_t)r * 512 + hc * 128 + col);
        }
        cp_commit();

        float acc1[2][4][4];
        #pragma unroll
        for (int m = 0; m < 2; m++)
            #pragma unroll
            for (int n = 0; n < 4; n++)
                #pragma unroll
                for (int q = 0; q < 4; q++) acc1[m][n][q] = 0.f;
        wgemm_l<2, 4, 8>(Yh, YPH, Wa, YPH, acc1, rb, nb, lane);

        #pragma unroll
        for (int n = 0; n < 4; n++) {
            int col = nb + n * 8 + 2 * i;
            float b0f = fc1b[hc * 128 + col];
            float b1f = fc1b[hc * 128 + col + 1];
            #pragma unroll
            for (int m = 0; m < 2; m++) {
                int row = rb + m * 16 + g;
                float v0 = acc1[m][n][0] + b0f;
                float v1 = acc1[m][n][1] + b1f;
                float v2 = acc1[m][n][2] + b0f;
                float v3 = acc1[m][n][3] + b1f;
                v0 = 0.5f * v0 * (1.0f + erff(v0 * is2));
                v1 = 0.5f * v1 * (1.0f + erff(v1 * is2));
                v2 = 0.5f * v2 * (1.0f + erff(v2 * is2));
                v3 = 0.5f * v3 * (1.0f + erff(v3 * is2));
                *(__half2*)(Hh + row * YPH + col)       = __floats2half2_rn(v0, v1);
                *(__half2*)(Hh + (row + 8) * YPH + col) = __floats2half2_rn(v2, v3);
            }
        }

        cp_wait0();
        __syncthreads();

        if (hc < 3) {
            const __half* src = g_fc1w_h + (size_t)(hc + 1) * 128 * DIM;
            #pragma unroll
            for (int it = 0; it < 4; it++) {
                int idx = tid + 512 * it;
                int r = idx >> 4;
                int col = (idx & 15) << 3;
                cp16(WaA + (r * YPH + col) * 2, src + r * DIM + col);
            }
            cp_commit();
        }

        wgemm_l<2, 4, 8>(Hh, YPH, Wb, YPH, acc2, rb, nb, lane);
    }

    __syncthreads();
    #pragma unroll
    for (int n = 0; n < 4; n++) {
        int col = nb + n * 8 + 2 * i;
        float b0f = fc2b[col];
        float b1f = fc2b[col + 1];
        #pragma unroll
        for (int m = 0; m < 2; m++) {
            int row = rb + m * 16 + g;
            h2[row * APAD + col]           = acc2[m][n][0] + b0f;
            h2[row * APAD + col + 1]       = acc2[m][n][1] + b1f;
            h2[(row + 8) * APAD + col]     = acc2[m][n][2] + b0f;
            h2[(row + 8) * APAD + col + 1] = acc2[m][n][3] + b1f;
        }
    }
    __syncthreads();

    {
        int row = tid >> 2;
        int cb = (tid & 3) * 32;
        float s = 0.f;
        #pragma unroll 8
        for (int c = 0; c < 32; c++) s += h2[row * APAD + cb + c];
        ps[tid] = s;
    }
    __syncthreads();
    if (tid < 128) {
        float s = ps[4 * tid] + ps[4 * tid + 1] + ps[4 * tid + 2] + ps[4 * tid + 3];
        muv[tid] = s * (1.0f / DIM);
    }
    __syncthreads();
    {
        int row = tid >> 2;
        int cb = (tid & 3) * 32;
        float m = muv[row];
        float v = 0.f;
        #pragma unroll 8
        for (int c = 0; c < 32; c++) {
            float d = h2[row * APAD + cb + c] - m;
            v += d * d;
        }
        ps[tid] = v;
    }
    __syncthreads();
    if (tid < 128) {
        float v = ps[4 * tid] + ps[4 * tid + 1] + ps[4 * tid + 2] + ps[4 * tid + 3];
        rsv[tid] = rsqrtf(v * (1.0f / DIM) + 1e-5f);
    }
    __syncthreads();

    float* od = out + tok0 * DIM;
    #pragma unroll
    for (int it = 0; it < 8; it++) {
        int e4 = tid + 512 * it;
        int t = e4 >> 5;
        int c = (e4 & 31) << 2;
        float4 yv = *(const float4*)(ysrc + (size_t)t * DIM + c);
        float m = muv[t], r = rsv[t];
        float4 o;
        o.x = yv.x + (h2[t * APAD + c + 0] - m) * r * n2w[c + 0] + n2b[c + 0];
        o.y = yv.y + (h2[t * APAD + c + 1] - m) * r * n2w[c + 1] + n2b[c + 1];
        o.z = yv.z + (h2[t * APAD + c + 2] - m) * r * n2w[c + 2] + n2b[c + 2];
        o.w = yv.w + (h2[t * APAD + c + 3] - m) * r * n2w[c + 3] + n2b[c + 3];
        *(float4*)(od + (size_t)t * DIM + c) = o;
    }
}

extern "C" void kernel_launch(void* const* d_in, const int* in_sizes, int n_in,
                              void* d_out, int out_size) {
    const float* x      = (const float*)d_in[0];
    const float* qkv_w  = (const float*)d_in[1];
    const float* qkv_b  = (const float*)d_in[2];
    const float* proj_w = (const float*)d_in[3];
    const float* proj_b = (const float*)d_in[4];
    const float* rpe_w1 = (const float*)d_in[5];
    const float* rpe_b1 = (const float*)d_in[6];
    const float* rpe_w2 = (const float*)d_in[7];
    const float* n1w    = (const float*)d_in[8];
    const float* n1b    = (const float*)d_in[9];
    const float* fc1w   = (const float*)d_in[10];
    const float* fc1b   = (const float*)d_in[11];
    const float* fc2w   = (const float*)d_in[12];
    const float* fc2b   = (const float*)d_in[13];
    const float* n2w    = (const float*)d_in[14];
    const float* n2b    = (const float*)d_in[15];
    float* out = (float*)d_out;

    cudaFuncSetAttribute(attn_kernel, cudaFuncAttributeMaxDynamicSharedMemorySize, ATTN_SMEM_BYTES);
    cudaFuncSetAttribute(mlp_kernel,  cudaFuncAttributeMaxDynamicSharedMemorySize, MLP_SMEM_BYTES);

    prep_fused_kernel<<<609, 128>>>(qkv_w, proj_w, fc1w, fc2w, rpe_w1, rpe_b1, rpe_w2);
    bias_scatter_kernel<<<64, 256>>>();
    attn_kernel<<<1024, 512, ATTN_SMEM_BYTES>>>(x, qkv_b, proj_b, n1w, n1b);
    mlp_kernel<<<1024, 512, MLP_SMEM_BYTES>>>(fc1b, fc2b, n2w, n2b, out);
}

// round 16
// speedup vs baseline: 1.0395x; 1.0395x over previous
#include <cuda_runtime.h>
#include <cuda_fp16.h>
#include <math.h>
#include <stdint.h>

#define WSZ 8
#define NHEAD 4
#define DIM 128
#define NTOK 64
#define HD 32
#define BATCH 32
#define HW 64
#define LSEQ 4096
#define RPE_HID 512
#define APAD 132
#define YPH 136    // fp16 smem pitch (halves)
#define PPH 72     // Vt fp16 pitch (halves)

__device__ float g_bias[NHEAD * NTOK * NTOK];
__device__ float g_ttab[225 * NHEAD];
__device__ float g_ybuf[(size_t)BATCH * LSEQ * DIM];
__device__ __half g_qkvw_h[3 * DIM * DIM];
__device__ __half g_projw_h[DIM * DIM];
__device__ __half g_fc1w_h[512 * DIM];
__device__ __half g_fc2w_h[DIM * 512];

// ---------------- fp16 MMA + ldmatrix helpers ----------------
__device__ __forceinline__ void mma_f16(float* c, const uint32_t* a, uint32_t b0, uint32_t b1) {
    asm volatile(
        "mma.sync.aligned.m16n8k16.row.col.f32.f16.f16.f32 "
        "{%0,%1,%2,%3}, {%4,%5,%6,%7}, {%8,%9}, {%0,%1,%2,%3};"
        : "+f"(c[0]), "+f"(c[1]), "+f"(c[2]), "+f"(c[3])
        : "r"(a[0]), "r"(a[1]), "r"(a[2]), "r"(a[3]), "r"(b0), "r"(b1));
}

__device__ __forceinline__ void ldsm_x4(uint32_t& r0, uint32_t& r1, uint32_t& r2, uint32_t& r3,
                                        uint32_t addr) {
    asm volatile("ldmatrix.sync.aligned.m8n8.x4.shared.b16 {%0,%1,%2,%3}, [%4];"
                 : "=r"(r0), "=r"(r1), "=r"(r2), "=r"(r3) : "r"(addr));
}

template<int MT, int NT, int KS>
__device__ __forceinline__ void wgemm_l(const __half* __restrict__ A, int lda,
                                        const __half* __restrict__ B, int ldb,
                                        float (&acc)[MT][NT][4], int rbase, int nbase, int lane)
{
    int lr = lane & 15;
    int lk = (lane >> 4) << 3;
    uint32_t ab[MT], bb[NT / 2];
    #pragma unroll
    for (int m = 0; m < MT; m++)
        ab[m] = (uint32_t)__cvta_generic_to_shared(A + (rbase + m * 16 + lr) * lda + lk);
    #pragma unroll
    for (int nn = 0; nn < NT / 2; nn++)
        bb[nn] = (uint32_t)__cvta_generic_to_shared(B + (nbase + nn * 16 + lr) * ldb + lk);
    #pragma unroll
    for (int ks = 0; ks < KS; ks++) {
        uint32_t a[MT][4];
        #pragma unroll
        for (int m = 0; m < MT; m++)
            ldsm_x4(a[m][0], a[m][1], a[m][2], a[m][3], ab[m] + ks * 32);
        #pragma unroll
        for (int nn = 0; nn < NT / 2; nn++) {
            uint32_t b0, b1, b2, b3;
            ldsm_x4(b0, b1, b2, b3, bb[nn] + ks * 32);
            #pragma unroll
            for (int m = 0; m < MT; m++) {
                mma_f16(acc[m][2 * nn],     a[m], b0, b2);
                mma_f16(acc[m][2 * nn + 1], a[m], b1, b3);
            }
        }
    }
}

// ---------------- cp.async helpers ----------------
__device__ __forceinline__ void cp16(uint32_t dst, const void* src) {
    asm volatile("cp.async.ca.shared.global [%0], [%1], 16;" :: "r"(dst), "l"(src));
}
__device__ __forceinline__ void cp_commit() { asm volatile("cp.async.commit_group;"); }
__device__ __forceinline__ void cp_wait0()  { asm volatile("cp.async.wait_group 0;"); }

// ---------------- fused prep: RPE table + weight fp16 conversion ----------------
__global__ void prep_fused_kernel(const float* __restrict__ qkvw, const float* __restrict__ projw,
                                  const float* __restrict__ fc1w, const float* __restrict__ fc2w,
                                  const float* __restrict__ w1, const float* __restrict__ b1,
                                  const float* __restrict__ w2) {
    int tid = threadIdx.x;
    if (blockIdx.x < 225) {
        __shared__ float4 red[128];
        int p = blockIdx.x;
        int i = p / 15, j = p % 15;
        float v0 = (float)(i - 7) / 7.0f * 8.0f;
        float v1 = (float)(j - 7) / 7.0f * 8.0f;
        float inv_l8 = 1.0f / log2f(8.0f);
        float s0 = (v0 > 0.f) ? 1.f : ((v0 < 0.f) ? -1.f : 0.f);
        float s1 = (v1 > 0.f) ? 1.f : ((v1 < 0.f) ? -1.f : 0.f);
        float x0 = s0 * log2f(fabsf(v0) + 1.0f) * inv_l8;
        float x1 = s1 * log2f(fabsf(v1) + 1.0f) * inv_l8;
        float a0 = 0.f, a1 = 0.f, a2 = 0.f, a3 = 0.f;
        #pragma unroll
        for (int r = 0; r < 4; r++) {
            int h = tid + 128 * r;
            float hid = x0 * w1[2 * h] + x1 * w1[2 * h + 1] + b1[h];
            hid = fmaxf(hid, 0.f);
            a0 += hid * w2[0 * RPE_HID + h];
            a1 += hid * w2[1 * RPE_HID + h];
            a2 += hid * w2[2 * RPE_HID + h];
            a3 += hid * w2[3 * RPE_HID + h];
        }
        red[tid] = make_float4(a0, a1, a2, a3);
        __syncthreads();
        for (int s = 64; s > 0; s >>= 1) {
            if (tid < s) {
                float4 o = red[tid + s];
                red[tid].x += o.x; red[tid].y += o.y; red[tid].z += o.z; red[tid].w += o.w;
            }
            __syncthreads();
        }
        if (tid == 0) {
            g_ttab[p * 4 + 0] = red[0].x; g_ttab[p * 4 + 1] = red[0].y;
            g_ttab[p * 4 + 2] = red[0].z; g_ttab[p * 4 + 3] = red[0].w;
        }
    } else {
        int e4 = (blockIdx.x - 225) * 128 + tid;   // 49152
        const float* src;
        __half* dst;
        int off;
        if (e4 < 12288)      { src = qkvw;  dst = g_qkvw_h;  off = e4; }
        else if (e4 < 16384) { src = projw; dst = g_projw_h; off = e4 - 12288; }
        else if (e4 < 32768) { src = fc1w;  dst = g_fc1w_h;  off = e4 - 16384; }
        else                 { src = fc2w;  dst = g_fc2w_h;  off = e4 - 32768; }
        float4 v = *(const float4*)(src + off * 4);
        *(__half2*)(dst + off * 4)     = __floats2half2_rn(v.x, v.y);
        *(__half2*)(dst + off * 4 + 2) = __floats2half2_rn(v.z, v.w);
    }
}

__global__ void bias_scatter_kernel() {
    int e = blockIdx.x * 256 + threadIdx.x;
    int h = e >> 12;
    int rem = e & 4095;
    int i = rem >> 6, j = rem & 63;
    int yi = i >> 3, xi = i & 7, yj = j >> 3, xj = j & 7;
    int idx = (yi - yj + 7) * 15 + (xi - xj + 7);
    g_bias[e] = g_ttab[idx * 4 + h];
}

// ---------------- Kernel 2: attention + LN1 + residual (R12 proven: 256 thr, 2 CTAs/SM) ----------------
#define AT_XW 0
#define AT_WB 17408
#define AT_QB 52224
#define AT_KB 69632
#define AT_VT 87040
#define AT_PS 105472
#define AT_RG 106496
#define AT_MU 106752
#define AT_RSTD 107008
#define ATTN_SMEM_BYTES 107264

__global__ __launch_bounds__(256, 2) void attn_kernel(
    const float* __restrict__ x, const float* __restrict__ qkv_b,
    const float* __restrict__ proj_b,
    const float* __restrict__ n1w, const float* __restrict__ n1b)
{
    extern __shared__ char smc[];
    __half* xw = (__half*)(smc + AT_XW);
    __half* ow = xw;
    __half* wb = (__half*)(smc + AT_WB);
    __half* qb = (__half*)(smc + AT_QB);
    __half* kb = (__half*)(smc + AT_KB);
    __half* vt = (__half*)(smc + AT_VT);
    float* ps = (float*)(smc + AT_PS);
    int* regid = (int*)(smc + AT_RG);
    float* mu = (float*)(smc + AT_MU);
    float* rstd = (float*)(smc + AT_RSTD);
    float* projf = (float*)(smc + AT_QB);   // overlay, pitch APAD

    uint32_t wbA = (uint32_t)__cvta_generic_to_shared(wb);

    int tid = threadIdx.x;
    int wid = tid >> 5;
    int lane = tid & 31;
    int g = lane >> 2;
    int i = lane & 3;

    int bx = blockIdx.x;
    int bimg = bx >> 6;
    int wh = (bx >> 3) & 7, ww = bx & 7;
    const float* xbase = x + (size_t)bimg * (LSEQ * DIM);

    // prefetch QKV chunk 0 -> wb
    #pragma unroll
    for (int it = 0; it < 8; it++) {
        int idx = tid + 256 * it;
        int r = idx >> 4;
        int col = (idx & 15) << 3;
        cp16(wbA + (r * YPH + col) * 2, g_qkvw_h + r * DIM + col);
    }
    cp_commit();

    // ---- load window (rolled -4) -> fp16 ----
    #pragma unroll
    for (int it = 0; it < 8; it++) {
        int e4 = tid + 256 * it;
        int t = e4 >> 5;
        int c = (e4 & 31) << 2;
        int ti = t >> 3, tj = t & 7;
        int hh = (wh * 8 + ti + 4) & 63;
        int wwp = (ww * 8 + tj + 4) & 63;
        float4 v = *(const float4*)(xbase + (size_t)((hh << 6) + wwp) * DIM + c);
        *(__half2*)(xw + t * YPH + c)     = __floats2half2_rn(v.x, v.y);
        *(__half2*)(xw + t * YPH + c + 2) = __floats2half2_rn(v.z, v.w);
    }
    if (tid < 64) {
        int ti = tid >> 3, tj = tid & 7;
        int ah = wh * 8 + ti, aw = ww * 8 + tj;
        int rh = ah < 56 ? 0 : (ah < 60 ? 1 : 2);
        int rw = aw < 56 ? 0 : (aw < 60 ? 1 : 2);
        regid[tid] = rh * 3 + rw;
    }

    const float scale = 0.17677669529663687f;

    // ---- QKV: 3 GEMMs 64x128 k=128, 8 warps 2Mx4N ----
    for (int cidx = 0; cidx < 3; cidx++) {
        cp_wait0();
        __syncthreads();

        float acc[2][4][4];
        #pragma unroll
        for (int m = 0; m < 2; m++)
            #pragma unroll
            for (int n = 0; n < 4; n++)
                #pragma unroll
                for (int q = 0; q < 4; q++) acc[m][n][q] = 0.f;
        int rbase = (wid >> 2) * 32;
        int nbase = (wid & 3) * 32;
        wgemm_l<2, 4, 8>(xw, YPH, wb, YPH, acc, rbase, nbase, lane);
        __syncthreads();   // wb reads done before next prefetch overwrites

        {
            const __half* nsrc = (cidx < 2) ? (g_qkvw_h + (cidx + 1) * DIM * DIM) : g_projw_h;
            #pragma unroll
            for (int it = 0; it < 8; it++) {
                int idx = tid + 256 * it;
                int r = idx >> 4;
                int col = (idx & 15) << 3;
                cp16(wbA + (r * YPH + col) * 2, nsrc + r * DIM + col);
            }
            cp_commit();
        }

        #pragma unroll
        for (int n = 0; n < 4; n++) {
            int col = nbase + n * 8 + 2 * i;
            float b0f = qkv_b[cidx * DIM + col];
            float b1f = qkv_b[cidx * DIM + col + 1];
            #pragma unroll
            for (int m = 0; m < 2; m++) {
                int row = rbase + m * 16 + g;
                float v0 = acc[m][n][0] + b0f;
                float v1 = acc[m][n][1] + b1f;
                float v2 = acc[m][n][2] + b0f;
                float v3 = acc[m][n][3] + b1f;
                if (cidx == 0) {
                    *(__half2*)(qb + row * YPH + col)       = __floats2half2_rn(v0 * scale, v1 * scale);
                    *(__half2*)(qb + (row + 8) * YPH + col) = __floats2half2_rn(v2 * scale, v3 * scale);
                } else if (cidx == 1) {
                    *(__half2*)(kb + row * YPH + col)       = __floats2half2_rn(v0, v1);
                    *(__half2*)(kb + (row + 8) * YPH + col) = __floats2half2_rn(v2, v3);
                } else {
                    vt[col * PPH + row]           = __float2half_rn(v0);
                    vt[(col + 1) * PPH + row]     = __float2half_rn(v1);
                    vt[col * PPH + row + 8]       = __float2half_rn(v2);
                    vt[(col + 1) * PPH + row + 8] = __float2half_rn(v3);
                }
            }
        }
        __syncthreads();
    }

    // ---- scores + register softmax + register P ----
    int h = wid >> 1;
    int hoff = h * HD;
    int rbase_h = (wid & 1) * 32;
    uint32_t pr[2][2][8];
    float rsinv[2][2];
    {
        float s[2][8][4];
        #pragma unroll
        for (int m = 0; m < 2; m++)
            #pragma unroll
            for (int n = 0; n < 8; n++)
                #pragma unroll
                for (int q = 0; q < 4; q++) s[m][n][q] = 0.f;
        wgemm_l<2, 8, 2>(qb + hoff, YPH, kb + hoff, YPH, s, rbase_h, 0, lane);

        const float* gb = g_bias + h * 4096;
        int cmask[8][2];
        #pragma unroll
        for (int n = 0; n < 8; n++) {
            cmask[n][0] = regid[n * 8 + 2 * i];
            cmask[n][1] = regid[n * 8 + 2 * i + 1];
        }
        #pragma unroll
        for (int m = 0; m < 2; m++) {
            #pragma unroll
            for (int ss = 0; ss < 2; ss++) {
                int row = rbase_h + m * 16 + 8 * ss + g;
                int rreg = regid[row];
                const float* gbr = gb + row * 64;
                float v[16];
                float mx = -1e30f;
                #pragma unroll
                for (int n = 0; n < 8; n++) {
                    int col = n * 8 + 2 * i;
                    float a0 = s[m][n][2 * ss]     + gbr[col]     + ((rreg != cmask[n][0]) ? -100.f : 0.f);
                    float a1 = s[m][n][2 * ss + 1] + gbr[col + 1] + ((rreg != cmask[n][1]) ? -100.f : 0.f);
                    v[2 * n] = a0; v[2 * n + 1] = a1;
                    mx = fmaxf(mx, fmaxf(a0, a1));
                }
                mx = fmaxf(mx, __shfl_xor_sync(0xFFFFFFFF, mx, 1));
                mx = fmaxf(mx, __shfl_xor_sync(0xFFFFFFFF, mx, 2));
                float sum = 0.f;
                #pragma unroll
                for (int n = 0; n < 8; n++) {
                    float e0 = __expf(v[2 * n] - mx);
                    float e1 = __expf(v[2 * n + 1] - mx);
                    sum += e0 + e1;
                    __half2 hp = __floats2half2_rn(e0, e1);
                    pr[m][ss][n] = *(uint32_t*)&hp;
                }
                sum += __shfl_xor_sync(0xFFFFFFFF, sum, 1);
                sum += __shfl_xor_sync(0xFFFFFFFF, sum, 2);
                rsinv[m][ss] = 1.0f / sum;
            }
        }
    }

    // ---- PV from register P ----
    {
        float o[2][4][4];
        #pragma unroll
        for (int m = 0; m < 2; m++)
            #pragma unroll
            for (int n = 0; n < 4; n++)
                #pragma unroll
                for (int q = 0; q < 4; q++) o[m][n][q] = 0.f;
        const __half* Vb = vt + hoff * PPH;
        int lr = lane & 15;
        int lk = (lane >> 4) << 3;
        uint32_t bb[2];
        #pragma unroll
        for (int nn = 0; nn < 2; nn++)
            bb[nn] = (uint32_t)__cvta_generic_to_shared(Vb + (nn * 16 + lr) * PPH + lk);
        #pragma unroll
        for (int ks = 0; ks < 4; ks++) {
            uint32_t a[2][4];
            #pragma unroll
            for (int m = 0; m < 2; m++) {
                a[m][0] = pr[m][0][2 * ks];
                a[m][1] = pr[m][1][2 * ks];
                a[m][2] = pr[m][0][2 * ks + 1];
                a[m][3] = pr[m][1][2 * ks + 1];
            }
            #pragma unroll
            for (int nn = 0; nn < 2; nn++) {
                uint32_t b0, b1, b2, b3;
                ldsm_x4(b0, b1, b2, b3, bb[nn] + ks * 32);
                #pragma unroll
                for (int m = 0; m < 2; m++) {
                    mma_f16(o[m][2 * nn],     a[m], b0, b2);
                    mma_f16(o[m][2 * nn + 1], a[m], b1, b3);
                }
            }
        }
        #pragma unroll
        for (int m = 0; m < 2; m++) {
            int row = rbase_h + m * 16 + g;
            float rs0 = rsinv[m][0];
            float rs1 = rsinv[m][1];
            #pragma unroll
            for (int n = 0; n < 4; n++) {
                int col = hoff + n * 8 + 2 * i;
                *(__half2*)(ow + row * YPH + col)       = __floats2half2_rn(o[m][n][0] * rs0, o[m][n][1] * rs0);
                *(__half2*)(ow + (row + 8) * YPH + col) = __floats2half2_rn(o[m][n][2] * rs1, o[m][n][3] * rs1);
            }
        }
    }
    cp_wait0();        // proj_w landed
    __syncthreads();

    // ---- proj GEMM 64x128 k=128 -> fp32 projf ----
    {
        float acc[2][4][4];
        #pragma unroll
        for (int m = 0; m < 2; m++)
            #pragma unroll
            for (int n = 0; n < 4; n++)
                #pragma unroll
                for (int q = 0; q < 4; q++) acc[m][n][q] = 0.f;
        int rbase = (wid >> 2) * 32;
        int nbase = (wid & 3) * 32;
        wgemm_l<2, 4, 8>(ow, YPH, wb, YPH, acc, rbase, nbase, lane);
        #pragma unroll
        for (int n = 0; n < 4; n++) {
            int col = nbase + n * 8 + 2 * i;
            float b0f = proj_b[col];
            float b1f = proj_b[col + 1];
            #pragma unroll
            for (int m = 0; m < 2; m++) {
                int row = rbase + m * 16 + g;
                projf[row * APAD + col]           = acc[m][n][0] + b0f;
                projf[row * APAD + col + 1]       = acc[m][n][1] + b1f;
                projf[(row + 8) * APAD + col]     = acc[m][n][2] + b0f;
                projf[(row + 8) * APAD + col + 1] = acc[m][n][3] + b1f;
            }
        }
    }
    __syncthreads();

    // ---- LN1 stats: 4 threads/row ----
    {
        int row = tid >> 2;
        int cb = (tid & 3) * 32;
        float s = 0.f;
        #pragma unroll 8
        for (int c = 0; c < 32; c++) s += projf[row * APAD + cb + c];
        ps[tid] = s;
    }
    __syncthreads();
    if (tid < 64) {
        float s = ps[4 * tid] + ps[4 * tid + 1] + ps[4 * tid + 2] + ps[4 * tid + 3];
        mu[tid] = s * (1.0f / DIM);
    }
    __syncthreads();
    {
        int row = tid >> 2;
        int cb = (tid & 3) * 32;
        float m = mu[row];
        float v = 0.f;
        #pragma unroll 8
        for (int c = 0; c < 32; c++) {
            float d = projf[row * APAD + cb + c] - m;
            v += d * d;
        }
        ps[tid] = v;
    }
    __syncthreads();
    if (tid < 64) {
        float v = ps[4 * tid] + ps[4 * tid + 1] + ps[4 * tid + 2] + ps[4 * tid + 3];
        rstd[tid] = rsqrtf(v * (1.0f / DIM) + 1e-5f);
    }
    __syncthreads();

    // ---- y = x + LN(proj) ----
    float* yb = g_ybuf + (size_t)bimg * (LSEQ * DIM);
    #pragma unroll
    for (int it = 0; it < 8; it++) {
        int e4 = tid + 256 * it;
        int t = e4 >> 5;
        int c = (e4 & 31) << 2;
        int ti = t >> 3, tj = t & 7;
        int hh = (wh * 8 + ti + 4) & 63;
        int wwp = (ww * 8 + tj + 4) & 63;
        size_t goff = (size_t)((hh << 6) + wwp) * DIM + c;
        float4 xv = *(const float4*)(xbase + goff);
        float m = mu[t], r = rstd[t];
        float4 o;
        o.x = xv.x + (projf[t * APAD + c + 0] - m) * r * n1w[c + 0] + n1b[c + 0];
        o.y = xv.y + (projf[t * APAD + c + 1] - m) * r * n1w[c + 1] + n1b[c + 1];
        o.z = xv.z + (projf[t * APAD + c + 2] - m) * r * n1w[c + 2] + n1b[c + 2];
        o.w = xv.w + (projf[t * APAD + c + 3] - m) * r * n1w[c + 3] + n1b[c + 3];
        *(float4*)(yb + goff) = o;
    }
}

// ---------------- Kernel 3: MLP + LN2 + residual (R12 proven: 512 thr, cp.async double-buffered) ----------------
#define MLP_SMEM_BYTES 142336

__global__ __launch_bounds__(512, 1) void mlp_kernel(
    const float* __restrict__ fc1b, const float* __restrict__ fc2b,
    const float* __restrict__ n2w, const float* __restrict__ n2b,
    float* __restrict__ out)
{
    extern __shared__ char smc[];
    __half* Yh = (__half*)smc;
    __half* Wa = (__half*)(smc + 34816);
    __half* Wb = (__half*)(smc + 69632);
    __half* Hh = (__half*)(smc + 104448);
    float* ps  = (float*)(smc + 139264);
    float* muv = ps + 512;
    float* rsv = muv + 128;
    float* h2  = (float*)smc;

    uint32_t WaA = (uint32_t)__cvta_generic_to_shared(Wa);
    uint32_t WbA = (uint32_t)__cvta_generic_to_shared(Wb);

    int tid = threadIdx.x;
    int wid = tid >> 5;
    int lane = tid & 31;
    int g = lane >> 2;
    int i = lane & 3;
    int rb = (wid >> 2) * 32;
    int nb = (wid & 3) * 32;

    size_t tok0 = (size_t)blockIdx.x * 128;
    const float* ysrc = g_ybuf + tok0 * DIM;

    #pragma unroll
    for (int it = 0; it < 4; it++) {
        int idx = tid + 512 * it;
        int r = idx >> 4;
        int col = (idx & 15) << 3;
        cp16(WaA + (r * YPH + col) * 2, g_fc1w_h + r * DIM + col);
    }
    cp_commit();

    #pragma unroll
    for (int it = 0; it < 8; it++) {
        int e4 = tid + 512 * it;
        int t = e4 >> 5;
        int c = (e4 & 31) << 2;
        float4 v = *(const float4*)(ysrc + (size_t)t * DIM + c);
        *(__half2*)(Yh + t * YPH + c)     = __floats2half2_rn(v.x, v.y);
        *(__half2*)(Yh + t * YPH + c + 2) = __floats2half2_rn(v.z, v.w);
    }

    float acc2[2][4][4];
    #pragma unroll
    for (int m = 0; m < 2; m++)
        #pragma unroll
        for (int n = 0; n < 4; n++)
            #pragma unroll
            for (int q = 0; q < 4; q++) acc2[m][n][q] = 0.f;

    const float is2 = 0.70710678118654752f;

    for (int hc = 0; hc < 4; hc++) {
        cp_wait0();
        __syncthreads();

        #pragma unroll
        for (int it = 0; it < 4; it++) {
            int idx = tid + 512 * it;
            int r = idx >> 4;
            int col = (idx & 15) << 3;
            cp16(WbA + (r * YPH + col) * 2, g_fc2w_h + (size_t)r * 512 + hc * 128 + col);
        }
        cp_commit();

        float acc1[2][4][4];
        #pragma unroll
        for (int m = 0; m < 2; m++)
            #pragma unroll
            for (int n = 0; n < 4; n++)
                #pragma unroll
                for (int q = 0; q < 4; q++) acc1[m][n][q] = 0.f;
        wgemm_l<2, 4, 8>(Yh, YPH, Wa, YPH, acc1, rb, nb, lane);

        #pragma unroll
        for (int n = 0; n < 4; n++) {
            int col = nb + n * 8 + 2 * i;
            float b0f = fc1b[hc * 128 + col];
            float b1f = fc1b[hc * 128 + col + 1];
            #pragma unroll
            for (int m = 0; m < 2; m++) {
                int row = rb + m * 16 + g;
                float v0 = acc1[m][n][0] + b0f;
                float v1 = acc1[m][n][1] + b1f;
                float v2 = acc1[m][n][2] + b0f;
                float v3 = acc1[m][n][3] + b1f;
                v0 = 0.5f * v0 * (1.0f + erff(v0 * is2));
                v1 = 0.5f * v1 * (1.0f + erff(v1 * is2));
                v2 = 0.5f * v2 * (1.0f + erff(v2 * is2));
                v3 = 0.5f * v3 * (1.0f + erff(v3 * is2));
                *(__half2*)(Hh + row * YPH + col)       = __floats2half2_rn(v0, v1);
                *(__half2*)(Hh + (row + 8) * YPH + col) = __floats2half2_rn(v2, v3);
            }
        }

        cp_wait0();
        __syncthreads();

        if (hc < 3) {
            const __half* src = g_fc1w_h + (size_t)(hc + 1) * 128 * DIM;
            #pragma unroll
            for (int it = 0; it < 4; it++) {
                int idx = tid + 512 * it;
                int r = idx >> 4;
                int col = (idx & 15) << 3;
                cp16(WaA + (r * YPH + col) * 2, src + r * DIM + col);
            }
            cp_commit();
        }

        wgemm_l<2, 4, 8>(Hh, YPH, Wb, YPH, acc2, rb, nb, lane);
    }

    __syncthreads();
    #pragma unroll
    for (int n = 0; n < 4; n++) {
        int col = nb + n * 8 + 2 * i;
        float b0f = fc2b[col];
        float b1f = fc2b[col + 1];
        #pragma unroll
        for (int m = 0; m < 2; m++) {
            int row = rb + m * 16 + g;
            h2[row * APAD + col]           = acc2[m][n][0] + b0f;
            h2[row * APAD + col + 1]       = acc2[m][n][1] + b1f;
            h2[(row + 8) * APAD + col]     = acc2[m][n][2] + b0f;
            h2[(row + 8) * APAD + col + 1] = acc2[m][n][3] + b1f;
        }
    }
    __syncthreads();

    {
        int row = tid >> 2;
        int cb = (tid & 3) * 32;
        float s = 0.f;
        #pragma unroll 8
        for (int c = 0; c < 32; c++) s += h2[row * APAD + cb + c];
        ps[tid] = s;
    }
    __syncthreads();
    if (tid < 128) {
        float s = ps[4 * tid] + ps[4 * tid + 1] + ps[4 * tid + 2] + ps[4 * tid + 3];
        muv[tid] = s * (1.0f / DIM);
    }
    __syncthreads();
    {
        int row = tid >> 2;
        int cb = (tid & 3) * 32;
        float m = muv[row];
        float v = 0.f;
        #pragma unroll 8
        for (int c = 0; c < 32; c++) {
            float d = h2[row * APAD + cb + c] - m;
            v += d * d;
        }
        ps[tid] = v;
    }
    __syncthreads();
    if (tid < 128) {
        float v = ps[4 * tid] + ps[4 * tid + 1] + ps[4 * tid + 2] + ps[4 * tid + 3];
        rsv[tid] = rsqrtf(v * (1.0f / DIM) + 1e-5f);
    }
    __syncthreads();

    float* od = out + tok0 * DIM;
    #pragma unroll
    for (int it = 0; it < 8; it++) {
        int e4 = tid + 512 * it;
        int t = e4 >> 5;
        int c = (e4 & 31) << 2;
        float4 yv = *(const float4*)(ysrc + (size_t)t * DIM + c);
        float m = muv[t], r = rsv[t];
        float4 o;
        o.x = yv.x + (h2[t * APAD + c + 0] - m) * r * n2w[c + 0] + n2b[c + 0];
        o.y = yv.y + (h2[t * APAD + c + 1] - m) * r * n2w[c + 1] + n2b[c + 1];
        o.z = yv.z + (h2[t * APAD + c + 2] - m) * r * n2w[c + 2] + n2b[c + 2];
        o.w = yv.w + (h2[t * APAD + c + 3] - m) * r * n2w[c + 3] + n2b[c + 3];
        *(float4*)(od + (size_t)t * DIM + c) = o;
    }
}

extern "C" void kernel_launch(void* const* d_in, const int* in_sizes, int n_in,
                              void* d_out, int out_size) {
    const float* x      = (const float*)d_in[0];
    const float* qkv_w  = (const float*)d_in[1];
    const float* qkv_b  = (const float*)d_in[2];
    const float* proj_w = (const float*)d_in[3];
    const float* proj_b = (const float*)d_in[4];
    const float* rpe_w1 = (const float*)d_in[5];
    const float* rpe_b1 = (const float*)d_in[6];
    const float* rpe_w2 = (const float*)d_in[7];
    const float* n1w    = (const float*)d_in[8];
    const float* n1b    = (const float*)d_in[9];
    const float* fc1w   = (const float*)d_in[10];
    const float* fc1b   = (const float*)d_in[11];
    const float* fc2w   = (const float*)d_in[12];
    const float* fc2b   = (const float*)d_in[13];
    const float* n2w    = (const float*)d_in[14];
    const float* n2b    = (const float*)d_in[15];
    float* out = (float*)d_out;

    cudaFuncSetAttribute(attn_kernel, cudaFuncAttributeMaxDynamicSharedMemorySize, ATTN_SMEM_BYTES);
    cudaFuncSetAttribute(mlp_kernel,  cudaFuncAttributeMaxDynamicSharedMemorySize, MLP_SMEM_BYTES);

    prep_fused_kernel<<<609, 128>>>(qkv_w, proj_w, fc1w, fc2w, rpe_w1, rpe_b1, rpe_w2);
    bias_scatter_kernel<<<64, 256>>>();
    attn_kernel<<<2048, 256, ATTN_SMEM_BYTES>>>(x, qkv_b, proj_b, n1w, n1b);
    mlp_kernel<<<1024, 512, MLP_SMEM_BYTES>>>(fc1b, fc2b, n2w, n2b, out);
}